// round 8
// baseline (speedup 1.0000x reference)
#include <cuda_runtime.h>
#include <cuda_bf16.h>
#include <math.h>

// Problem dims (fixed by the reference)
#define E     1024
#define H     2048
#define G     8192     // 4*H gate rows
#define TT    128      // title timesteps
#define TA    16       // author timesteps
#define NB    148      // persistent grid: one block per SM (B300=148, GB300=152 SMs)
#define UPB   14       // hidden units per block (148*14 = 2072 >= 2048)
#define WELEM ((size_t)G * H)   // 16,777,216 elements per W_hh

// ---------------- device scratch (no allocation allowed) ----------------
__device__ __align__(16) float g_gx_t[TT * G];     // x-side gates + bias (title)
__device__ __align__(16) float g_gx_a[TA * G];     // x-side gates + bias (authors)
__device__ __align__(16) __nv_bfloat16 g_Whh_bf[2 * WELEM];  // [0]=title [1]=authors (64 MB)
__device__ __align__(16) float g_h_t[2 * H];       // title h ping-pong
__device__ __align__(16) float g_h_a[2 * H];       // authors h ping-pong
__device__ __align__(16) float g_h1[H];
__device__ __align__(16) float g_h2[H];
__device__ unsigned g_arrive;
__device__ unsigned g_gen;

// ---------------- packed f32x2 + bf16 helpers ----------------
__device__ __forceinline__ unsigned long long packf2(float x, float y) {
    unsigned long long d;
    asm("mov.b64 %0, {%1, %2};" : "=l"(d) : "f"(x), "f"(y));
    return d;
}
__device__ __forceinline__ void unpackf2(unsigned long long d, float& x, float& y) {
    asm("mov.b64 {%0, %1}, %2;" : "=f"(x), "=f"(y) : "l"(d));
}
__device__ __forceinline__ void ffma2(unsigned long long& d, unsigned long long a, unsigned long long b) {
    asm("fma.rn.f32x2 %0, %1, %2, %0;" : "+l"(d) : "l"(a), "l"(b));
}
__device__ __forceinline__ unsigned long long addf2(unsigned long long a, unsigned long long b) {
    unsigned long long d;
    asm("add.rn.f32x2 %0, %1, %2;" : "=l"(d) : "l"(a), "l"(b));
    return d;
}
// bf16x2 word -> packed f32x2 {lo,hi} via 2 PRMT (bf16->f32 is a 16-bit left shift)
__device__ __forceinline__ unsigned long long b2f2(unsigned w) {
    unsigned lo, hi, z = 0u;
    asm("prmt.b32 %0, %1, %2, 0x1044;" : "=r"(lo) : "r"(w), "r"(z));
    asm("prmt.b32 %0, %1, %2, 0x3244;" : "=r"(hi) : "r"(w), "r"(z));
    unsigned long long d;
    asm("mov.b64 %0, {%1, %2};" : "=l"(d) : "r"(lo), "r"(hi));
    return d;
}

// ---------------- init: zero h buffers + barrier counters ----------------
__global__ void init_kernel() {
    int i = blockIdx.x * blockDim.x + threadIdx.x;
    if (i < 2 * H)          g_h_t[i] = 0.f;
    else if (i < 4 * H)     g_h_a[i - 2 * H] = 0.f;
    if (i == 0) { g_arrive = 0u; g_gen = 0u; }
}

// ---------------- x-side GEMM (gather fused): C[T x G] = emb[idx] @ W^T + (b_ih+b_hh) ----
// Block tile: 64 gate rows x (16*TR) timesteps, 256 threads, thread tile 4j x TR.
template<int TR>
__global__ __launch_bounds__(256) void gemm_x_kernel(const int* __restrict__ idx,
                                                     const float* __restrict__ emb,
                                                     const float* __restrict__ W,
                                                     const float* __restrict__ bih,
                                                     const float* __restrict__ bhh) {
    constexpr int TTILE = 16 * TR;
    float* __restrict__ C = (TR == 8) ? g_gx_t : g_gx_a;

    __shared__ float Xs[32][TTILE + 4];
    __shared__ float Ws[32][68];
    __shared__ int idx_s[TTILE];

    const int tid = threadIdx.x;
    const int j0 = blockIdx.x * 64;
    for (int i = tid; i < TTILE; i += 256) idx_s[i] = idx[i];
    __syncthreads();

    const int jj = (tid & 15) * 4;
    const int ti = (tid >> 4) * TR;

    float acc[4][TR];
#pragma unroll
    for (int a = 0; a < 4; a++)
#pragma unroll
        for (int t = 0; t < TR; t++) acc[a][t] = 0.f;

    for (int k0 = 0; k0 < E; k0 += 32) {
        for (int e = tid; e < 32 * TTILE; e += 256) {
            int k = e & 31, t = e >> 5;
            Xs[k][t] = emb[(size_t)idx_s[t] * E + k0 + k];
        }
        for (int e = tid; e < 2048; e += 256) {
            int k = e & 31, j = e >> 5;
            Ws[k][j] = W[(size_t)(j0 + j) * E + k0 + k];
        }
        __syncthreads();
#pragma unroll
        for (int k = 0; k < 32; k++) {
            float4 wv = *(const float4*)&Ws[k][jj];
            if constexpr (TR == 8) {
                float4 x0 = *(const float4*)&Xs[k][ti];
                float4 x1 = *(const float4*)&Xs[k][ti + 4];
                float xv[8] = {x0.x, x0.y, x0.z, x0.w, x1.x, x1.y, x1.z, x1.w};
                float wa[4] = {wv.x, wv.y, wv.z, wv.w};
#pragma unroll
                for (int a = 0; a < 4; a++)
#pragma unroll
                    for (int t = 0; t < 8; t++) acc[a][t] = fmaf(wa[a], xv[t], acc[a][t]);
            } else {
                float xv = Xs[k][ti];
                acc[0][0] = fmaf(wv.x, xv, acc[0][0]);
                acc[1][0] = fmaf(wv.y, xv, acc[1][0]);
                acc[2][0] = fmaf(wv.z, xv, acc[2][0]);
                acc[3][0] = fmaf(wv.w, xv, acc[3][0]);
            }
        }
        __syncthreads();
    }

#pragma unroll
    for (int a = 0; a < 4; a++) {
        int j = j0 + jj + a;
        float bias = bih[j] + bhh[j];
#pragma unroll
        for (int t = 0; t < TR; t++)
            C[(size_t)(ti + t) * G + j] = acc[a][t] + bias;
    }
}

// ---------------- persistent kernel pieces ----------------
__device__ __forceinline__ void grid_barrier(unsigned target) {
    __syncthreads();
    if (threadIdx.x == 0) {
        __threadfence();
        unsigned old = atomicAdd(&g_arrive, 1u);
        if (old == NB - 1) {
            g_arrive = 0u;              // all arrived; safe to reset before publish
            __threadfence();
            atomicExch(&g_gen, target);
        } else {
            while (*(volatile unsigned*)&g_gen < target) { }
        }
        __threadfence();
    }
    __syncthreads();
}

// stage h (2048 floats) into smem, bypassing (incoherent) L1
__device__ __forceinline__ void stage_h(float* dst, const float* src, int tid) {
    const float4* s4 = (const float4*)src;
    float4* d4 = (float4*)dst;
    for (int i = tid; i < H / 4; i += 256) d4[i] = __ldcg(s4 + i);
}

// compute this block's 4*nu gate pre-activations: sg[r] = W_row . h + gx[row]
__device__ __forceinline__ void do_rows(const __nv_bfloat16* __restrict__ Wb,
                                        const float* __restrict__ gx,
                                        float* __restrict__ sg,
                                        const float* __restrict__ shv,
                                        int u0, int nu, int warp, int lane) {
    // pre-pack h into 32 f32x2 registers (64 floats/lane), reused for all rows
    unsigned long long hp[32];
    const float4* sh4 = (const float4*)shv;
#pragma unroll
    for (int k = 0; k < 8; k++) {
        int c = (k << 5) + lane;         // 8-elem chunk index owned by this lane
        float4 f0 = sh4[2 * c];
        float4 f1 = sh4[2 * c + 1];
        hp[4 * k + 0] = packf2(f0.x, f0.y);
        hp[4 * k + 1] = packf2(f0.z, f0.w);
        hp[4 * k + 2] = packf2(f1.x, f1.y);
        hp[4 * k + 3] = packf2(f1.z, f1.w);
    }
    for (int r = warp; r < 4 * nu; r += 8) {
        int ul = r >> 2, gate = r & 3;
        const uint4* wrow = (const uint4*)(Wb + ((size_t)gate * H + u0 + ul) * H);
        uint4 wv[8];
#pragma unroll
        for (int k = 0; k < 8; k++) wv[k] = wrow[(k << 5) + lane];
        unsigned long long a0 = 0, a1 = 0, a2 = 0, a3 = 0;
#pragma unroll
        for (int k = 0; k < 8; k++) {
            ffma2(a0, b2f2(wv[k].x), hp[4 * k + 0]);
            ffma2(a1, b2f2(wv[k].y), hp[4 * k + 1]);
            ffma2(a2, b2f2(wv[k].z), hp[4 * k + 2]);
            ffma2(a3, b2f2(wv[k].w), hp[4 * k + 3]);
        }
        unsigned long long s2 = addf2(addf2(a0, a1), addf2(a2, a3));
        float lo, hi;
        unpackf2(s2, lo, hi);
        float s = lo + hi;
#pragma unroll
        for (int off = 16; off; off >>= 1) s += __shfl_xor_sync(0xFFFFFFFFu, s, off);
        if (lane == 0) sg[r] = s + __ldg(gx + (size_t)gate * H + u0 + ul);
    }
}

__device__ __forceinline__ void pointwise(const float* sg, float* c_s, float* h_dst, int u_loc) {
    float gi = sg[4 * u_loc + 0];
    float gf = sg[4 * u_loc + 1];
    float gg = sg[4 * u_loc + 2];
    float go = sg[4 * u_loc + 3];
    float iv = 1.f / (1.f + expf(-gi));
    float fv = 1.f / (1.f + expf(-gf));
    float gv = tanhf(gg);
    float ov = 1.f / (1.f + expf(-go));
    float cn = fv * c_s[u_loc] + iv * gv;
    c_s[u_loc] = cn;
    *h_dst = ov * tanhf(cn);
}

// warp computes dot(Wrow[0..K), sh[0..K)) -> returns full sum on all lanes
__device__ __forceinline__ float warp_dot(const float* __restrict__ Wrow,
                                          const float* __restrict__ shv, int K, int lane) {
    const float4* w4 = (const float4*)Wrow;
    const float4* s4 = (const float4*)shv;
    float acc = 0.f;
    for (int i = lane; i < K / 4; i += 32) {
        float4 w = w4[i], x = s4[i];
        acc = fmaf(w.x, x.x, fmaf(w.y, x.y, fmaf(w.z, x.z, fmaf(w.w, x.w, acc))));
    }
#pragma unroll
    for (int off = 16; off; off >>= 1) acc += __shfl_xor_sync(0xFFFFFFFFu, acc, off);
    return acc;
}

// ---------------- persistent kernel: convert + recurrence + MLP ----------------
__global__ __launch_bounds__(256, 1) void lstm_persist_kernel(
        const float* __restrict__ Wt_hh, const float* __restrict__ Wa_hh,
        const float* __restrict__ W1, const float* __restrict__ b1,
        const float* __restrict__ W2, const float* __restrict__ b2,
        const float* __restrict__ W3, const float* __restrict__ b3,
        float* __restrict__ out) {
    __shared__ __align__(16) float sh[2 * H];   // 16 KB staging (2H for MLP concat)
    __shared__ float sgT[4 * UPB], sgA[4 * UPB];
    __shared__ float cT[UPB], cA[UPB];

    const int tid = threadIdx.x, warp = tid >> 5, lane = tid & 31;
    const int b = blockIdx.x;
    const int u0 = b * UPB;
    int nu = 2048 - u0;
    if (nu < 0) nu = 0;
    if (nu > UPB) nu = UPB;

    // ---- prologue: convert OWN rows of both W_hh to bf16 (block-local, no sync needed) ----
    for (int r = 0; r < 4 * nu; r++) {
        int ul = r >> 2, gate = r & 3;
        size_t row = (size_t)gate * H + u0 + ul;
        const float4* s1 = (const float4*)(Wt_hh + row * H);
        const float4* s2 = (const float4*)(Wa_hh + row * H);
        uint2* d1 = (uint2*)(g_Whh_bf + row * H);
        uint2* d2 = (uint2*)(g_Whh_bf + WELEM + row * H);
        for (int e = tid; e < H / 4; e += 256) {
            float4 f = s1[e];
            __nv_bfloat162 p0 = __float22bfloat162_rn(make_float2(f.x, f.y));
            __nv_bfloat162 p1 = __float22bfloat162_rn(make_float2(f.z, f.w));
            uint2 o; o.x = *(unsigned*)&p0; o.y = *(unsigned*)&p1;
            d1[e] = o;
            f = s2[e];
            p0 = __float22bfloat162_rn(make_float2(f.x, f.y));
            p1 = __float22bfloat162_rn(make_float2(f.z, f.w));
            o.x = *(unsigned*)&p0; o.y = *(unsigned*)&p1;
            d2[e] = o;
        }
    }
    if (tid < UPB) { cT[tid] = 0.f; cA[tid] = 0.f; }
    __syncthreads();

    unsigned bar = 0;

    // ---- recurrence ----
    for (int t = 0; t < TT; t++) {
        // title stream
        stage_h(sh, g_h_t + (size_t)(t & 1) * H, tid);
        __syncthreads();
        do_rows(g_Whh_bf, g_gx_t + (size_t)t * G, sgT, sh, u0, nu, warp, lane);
        __syncthreads();
        // authors stream (first 16 steps)
        if (t < TA) {
            stage_h(sh, g_h_a + (size_t)(t & 1) * H, tid);
            __syncthreads();
            do_rows(g_Whh_bf + WELEM, g_gx_a + (size_t)t * G, sgA, sh, u0, nu, warp, lane);
            __syncthreads();
        }
        if (tid < nu) {
            pointwise(sgT, cT, g_h_t + (size_t)((t + 1) & 1) * H + u0 + tid, tid);
            if (t < TA)
                pointwise(sgA, cA, g_h_a + (size_t)((t + 1) & 1) * H + u0 + tid, tid);
        }
        bar++;
        grid_barrier(bar);   // publishes h for everyone; also orders next-step reads
    }
    // final title h is in g_h_t[0..H) (128 even), final authors h in g_h_a[0..H) (16 even)

    // ---- MLP layer 1: h1 = relu([hT;hA] @ W1^T + b1) ----
    {
        const float4* t4 = (const float4*)g_h_t;
        const float4* a4 = (const float4*)g_h_a;
        float4* d4 = (float4*)sh;
        for (int i = tid; i < H / 4; i += 256) {
            d4[i]         = __ldcg(t4 + i);
            d4[H / 4 + i] = __ldcg(a4 + i);
        }
        __syncthreads();
        for (int r = warp; r < nu; r += 8) {
            int row = u0 + r;
            float s = warp_dot(W1 + (size_t)row * 2 * H, sh, 2 * H, lane);
            if (lane == 0) g_h1[row] = fmaxf(s + __ldg(b1 + row), 0.f);
        }
        bar++;
        grid_barrier(bar);
    }
    // ---- MLP layer 2 ----
    {
        const float4* s4 = (const float4*)g_h1;
        float4* d4 = (float4*)sh;
        for (int i = tid; i < H / 4; i += 256) d4[i] = __ldcg(s4 + i);
        __syncthreads();
        for (int r = warp; r < nu; r += 8) {
            int row = u0 + r;
            float s = warp_dot(W2 + (size_t)row * H, sh, H, lane);
            if (lane == 0) g_h2[row] = fmaxf(s + __ldg(b2 + row), 0.f);
        }
        bar++;
        grid_barrier(bar);
    }
    // ---- MLP layer 3 (block 0 only) ----
    if (b == 0) {
        const float4* s4 = (const float4*)g_h2;
        float4* d4 = (float4*)sh;
        for (int i = tid; i < H / 4; i += 256) d4[i] = __ldcg(s4 + i);
        __syncthreads();
        if (warp < 2) {
            float s = warp_dot(W3 + (size_t)warp * H, sh, H, lane);
            if (lane == 0) out[warp] = s + __ldg(b3 + warp);
        }
    }
}

// ---------------- launcher ----------------
extern "C" void kernel_launch(void* const* d_in, const int* in_sizes, int n_in,
                              void* d_out, int out_size) {
    const int*   x_title   = (const int*)  d_in[0];
    const int*   x_authors = (const int*)  d_in[1];
    const float* emb_t     = (const float*)d_in[2];
    const float* emb_a     = (const float*)d_in[3];
    const float* W_ih_t    = (const float*)d_in[4];
    const float* W_hh_t    = (const float*)d_in[5];
    const float* b_ih_t    = (const float*)d_in[6];
    const float* b_hh_t    = (const float*)d_in[7];
    const float* W_ih_a    = (const float*)d_in[8];
    const float* W_hh_a    = (const float*)d_in[9];
    const float* b_ih_a    = (const float*)d_in[10];
    const float* b_hh_a    = (const float*)d_in[11];
    const float* W1        = (const float*)d_in[12];
    const float* b1        = (const float*)d_in[13];
    const float* W2        = (const float*)d_in[14];
    const float* b2        = (const float*)d_in[15];
    const float* W3        = (const float*)d_in[16];
    const float* b3        = (const float*)d_in[17];
    float* out = (float*)d_out;

    init_kernel<<<(4 * H + 255) / 256, 256>>>();
    gemm_x_kernel<8><<<G / 64, 256>>>(x_title,   emb_t, W_ih_t, b_ih_t, b_hh_t);
    gemm_x_kernel<1><<<G / 64, 256>>>(x_authors, emb_a, W_ih_a, b_ih_a, b_hh_a);
    lstm_persist_kernel<<<NB, 256>>>(W_hh_t, W_hh_a, W1, b1, W2, b2, W3, b3, out);
}

// round 9
// speedup vs baseline: 1.1866x; 1.1866x over previous
#include <cuda_runtime.h>
#include <cuda_bf16.h>
#include <math.h>

// Problem dims (fixed by the reference)
#define E     1024
#define H     2048
#define G     8192     // 4*H gate rows
#define TT    128      // title timesteps
#define TA    16       // author timesteps
#define NB    148      // persistent grid: one block per SM
#define NT    512      // threads per block (16 warps)
#define UPB   14       // hidden units per block (148*14 = 2072 >= 2048)
#define WELEM ((size_t)G * H)   // 16,777,216 elements per W_hh

// ---------------- device scratch (no allocation allowed) ----------------
__device__ __align__(16) float g_gx_t[TT * G];     // x-side gates + bias (title)
__device__ __align__(16) float g_gx_a[TA * G];     // x-side gates + bias (authors)
__device__ __align__(16) __nv_bfloat16 g_Whh_bf[2 * WELEM];  // [0]=title [1]=authors (64 MB)
__device__ __align__(16) float g_h_t[2 * H];       // title h ping-pong
__device__ __align__(16) float g_h_a[2 * H];       // authors h ping-pong
__device__ __align__(16) float g_h1[H];
__device__ __align__(16) float g_h2[H];
__device__ unsigned g_arrive;
__device__ unsigned g_gen;

// ---------------- packed f32x2 + bf16 helpers ----------------
typedef unsigned long long ull;
__device__ __forceinline__ ull packf2(float x, float y) {
    ull d; asm("mov.b64 %0, {%1, %2};" : "=l"(d) : "f"(x), "f"(y)); return d;
}
__device__ __forceinline__ void unpackf2(ull d, float& x, float& y) {
    asm("mov.b64 {%0, %1}, %2;" : "=f"(x), "=f"(y) : "l"(d));
}
__device__ __forceinline__ void ffma2(ull& d, ull a, ull b) {
    asm("fma.rn.f32x2 %0, %1, %2, %0;" : "+l"(d) : "l"(a), "l"(b));
}
__device__ __forceinline__ ull addf2(ull a, ull b) {
    ull d; asm("add.rn.f32x2 %0, %1, %2;" : "=l"(d) : "l"(a), "l"(b)); return d;
}
// bf16x2 word -> packed f32x2 {lo,hi} via 2 PRMT (bf16->f32 == 16-bit left shift)
__device__ __forceinline__ ull b2f2(unsigned w) {
    unsigned lo, hi, z = 0u;
    asm("prmt.b32 %0, %1, %2, 0x1044;" : "=r"(lo) : "r"(w), "r"(z));
    asm("prmt.b32 %0, %1, %2, 0x3244;" : "=r"(hi) : "r"(w), "r"(z));
    ull d; asm("mov.b64 %0, {%1, %2};" : "=l"(d) : "r"(lo), "r"(hi));
    return d;
}

// ---------------- init: zero h buffers + barrier counters ----------------
__global__ void init_kernel() {
    int i = blockIdx.x * blockDim.x + threadIdx.x;
    if (i < 2 * H)          g_h_t[i] = 0.f;
    else if (i < 4 * H)     g_h_a[i - 2 * H] = 0.f;
    if (i == 0) { g_arrive = 0u; g_gen = 0u; }
}

// ---------------- x-side GEMM (gather fused): C[T x G] = emb[idx] @ W^T + (b_ih+b_hh) ----
template<int TR>
__global__ __launch_bounds__(256) void gemm_x_kernel(const int* __restrict__ idx,
                                                     const float* __restrict__ emb,
                                                     const float* __restrict__ W,
                                                     const float* __restrict__ bih,
                                                     const float* __restrict__ bhh) {
    constexpr int TTILE = 16 * TR;
    float* __restrict__ C = (TR == 8) ? g_gx_t : g_gx_a;

    __shared__ float Xs[32][TTILE + 4];
    __shared__ float Ws[32][68];
    __shared__ int idx_s[TTILE];

    const int tid = threadIdx.x;
    const int j0 = blockIdx.x * 64;
    for (int i = tid; i < TTILE; i += 256) idx_s[i] = idx[i];
    __syncthreads();

    const int jj = (tid & 15) * 4;
    const int ti = (tid >> 4) * TR;

    float acc[4][TR];
#pragma unroll
    for (int a = 0; a < 4; a++)
#pragma unroll
        for (int t = 0; t < TR; t++) acc[a][t] = 0.f;

    for (int k0 = 0; k0 < E; k0 += 32) {
        for (int e = tid; e < 32 * TTILE; e += 256) {
            int k = e & 31, t = e >> 5;
            Xs[k][t] = emb[(size_t)idx_s[t] * E + k0 + k];
        }
        for (int e = tid; e < 2048; e += 256) {
            int k = e & 31, j = e >> 5;
            Ws[k][j] = W[(size_t)(j0 + j) * E + k0 + k];
        }
        __syncthreads();
#pragma unroll
        for (int k = 0; k < 32; k++) {
            float4 wv = *(const float4*)&Ws[k][jj];
            if constexpr (TR == 8) {
                float4 x0 = *(const float4*)&Xs[k][ti];
                float4 x1 = *(const float4*)&Xs[k][ti + 4];
                float xv[8] = {x0.x, x0.y, x0.z, x0.w, x1.x, x1.y, x1.z, x1.w};
                float wa[4] = {wv.x, wv.y, wv.z, wv.w};
#pragma unroll
                for (int a = 0; a < 4; a++)
#pragma unroll
                    for (int t = 0; t < 8; t++) acc[a][t] = fmaf(wa[a], xv[t], acc[a][t]);
            } else {
                float xv = Xs[k][ti];
                acc[0][0] = fmaf(wv.x, xv, acc[0][0]);
                acc[1][0] = fmaf(wv.y, xv, acc[1][0]);
                acc[2][0] = fmaf(wv.z, xv, acc[2][0]);
                acc[3][0] = fmaf(wv.w, xv, acc[3][0]);
            }
        }
        __syncthreads();
    }

#pragma unroll
    for (int a = 0; a < 4; a++) {
        int j = j0 + jj + a;
        float bias = bih[j] + bhh[j];
#pragma unroll
        for (int t = 0; t < TR; t++)
            C[(size_t)(ti + t) * G + j] = acc[a][t] + bias;
    }
}

// ---------------- persistent kernel pieces ----------------
__device__ __forceinline__ void grid_barrier(unsigned target) {
    __syncthreads();
    if (threadIdx.x == 0) {
        __threadfence();
        unsigned old = atomicAdd(&g_arrive, 1u);
        if (old == NB - 1) {
            g_arrive = 0u;
            __threadfence();
            atomicExch(&g_gen, target);
        } else {
            while (*(volatile unsigned*)&g_gen < target) { }
        }
        __threadfence();
    }
    __syncthreads();
}

// stage h into SPLIT smem layout: shA[c] = h4[2c], shB[c] = h4[2c+1], c in [0,512)
// -> per-k LDS with 16B lane stride (conflict-free). __ldcg bypasses stale L1.
__device__ __forceinline__ void stage_h_split(float4* shA4, float4* shB4,
                                              const float* src, int tid) {
    const float4* s4 = (const float4*)src;
    for (int i = tid; i < H / 8; i += NT) {
        shA4[i] = __ldcg(s4 + 2 * i);
        shB4[i] = __ldcg(s4 + 2 * i + 1);
    }
}

// compute this block's 4*nu gate pre-activations, two rows per warp pass
__device__ __forceinline__ void do_rows(const __nv_bfloat16* __restrict__ Wb,
                                        const float* __restrict__ gx,
                                        float* __restrict__ sg,
                                        const float4* __restrict__ shA4,
                                        const float4* __restrict__ shB4,
                                        int u0, int nu, int warp, int lane) {
    for (int p = warp; p < 2 * nu; p += 16) {
        const int r0 = 2 * p, r1 = r0 + 1;
        const int ul0 = r0 >> 2, g0 = r0 & 3;
        const int ul1 = r1 >> 2, g1 = r1 & 3;
        const uint4* wa = (const uint4*)(Wb + ((size_t)g0 * H + u0 + ul0) * H);
        const uint4* wb = (const uint4*)(Wb + ((size_t)g1 * H + u0 + ul1) * H);
        uint4 va[8], vb[8];
#pragma unroll
        for (int k = 0; k < 8; k++) {
            va[k] = wa[(k << 5) + lane];
            vb[k] = wb[(k << 5) + lane];
        }
        ull a0 = 0, a1 = 0, b0 = 0, b1 = 0;
#pragma unroll
        for (int k = 0; k < 8; k++) {
            int c = (k << 5) + lane;
            float4 hA = shA4[c], hB = shB4[c];
            ull h0 = packf2(hA.x, hA.y), h1 = packf2(hA.z, hA.w);
            ull h2 = packf2(hB.x, hB.y), h3 = packf2(hB.z, hB.w);
            ffma2(a0, b2f2(va[k].x), h0); ffma2(a1, b2f2(va[k].y), h1);
            ffma2(a0, b2f2(va[k].z), h2); ffma2(a1, b2f2(va[k].w), h3);
            ffma2(b0, b2f2(vb[k].x), h0); ffma2(b1, b2f2(vb[k].y), h1);
            ffma2(b0, b2f2(vb[k].z), h2); ffma2(b1, b2f2(vb[k].w), h3);
        }
        float xa, ya, xb, yb;
        unpackf2(addf2(a0, a1), xa, ya);
        unpackf2(addf2(b0, b1), xb, yb);
        float sa = xa + ya, sb = xb + yb;
#pragma unroll
        for (int off = 16; off; off >>= 1) {
            sa += __shfl_xor_sync(0xFFFFFFFFu, sa, off);
            sb += __shfl_xor_sync(0xFFFFFFFFu, sb, off);
        }
        if (lane == 0) {
            sg[r0] = sa + __ldg(gx + (size_t)g0 * H + u0 + ul0);
            sg[r1] = sb + __ldg(gx + (size_t)g1 * H + u0 + ul1);
        }
    }
}

__device__ __forceinline__ void pointwise(const float* sg, float* c_s, float* h_dst, int u_loc) {
    float gi = sg[4 * u_loc + 0];
    float gf = sg[4 * u_loc + 1];
    float gg = sg[4 * u_loc + 2];
    float go = sg[4 * u_loc + 3];
    float iv = 1.f / (1.f + expf(-gi));
    float fv = 1.f / (1.f + expf(-gf));
    float gv = tanhf(gg);
    float ov = 1.f / (1.f + expf(-go));
    float cn = fv * c_s[u_loc] + iv * gv;
    c_s[u_loc] = cn;
    *h_dst = ov * tanhf(cn);
}

__device__ __forceinline__ float warp_dot(const float* __restrict__ Wrow,
                                          const float* __restrict__ shv, int K, int lane) {
    const float4* w4 = (const float4*)Wrow;
    const float4* s4 = (const float4*)shv;
    float acc = 0.f;
    for (int i = lane; i < K / 4; i += 32) {
        float4 w = w4[i], x = s4[i];
        acc = fmaf(w.x, x.x, fmaf(w.y, x.y, fmaf(w.z, x.z, fmaf(w.w, x.w, acc))));
    }
#pragma unroll
    for (int off = 16; off; off >>= 1) acc += __shfl_xor_sync(0xFFFFFFFFu, acc, off);
    return acc;
}

// ---------------- persistent kernel: convert + recurrence + MLP ----------------
__global__ __launch_bounds__(NT, 1) void lstm_persist_kernel(
        const float* __restrict__ Wt_hh, const float* __restrict__ Wa_hh,
        const float* __restrict__ W1, const float* __restrict__ b1,
        const float* __restrict__ W2, const float* __restrict__ b2,
        const float* __restrict__ W3, const float* __restrict__ b3,
        float* __restrict__ out) {
    __shared__ __align__(16) float sh[2 * H];   // 16 KB: split h staging / MLP concat
    __shared__ float sgT[4 * UPB], sgA[4 * UPB];
    __shared__ float cT[UPB], cA[UPB];

    const int tid = threadIdx.x, warp = tid >> 5, lane = tid & 31;
    const int b = blockIdx.x;
    const int u0 = b * UPB;
    int nu = 2048 - u0;
    if (nu < 0) nu = 0;
    if (nu > UPB) nu = UPB;

    float4* shA4 = (float4*)sh;
    float4* shB4 = (float4*)(sh + H);

    // ---- prologue: convert OWN rows of both W_hh to bf16 (flat, vectorized) ----
#pragma unroll
    for (int g = 0; g < 4; g++) {
        size_t base4 = (((size_t)g * H + u0) * H) >> 2;   // float4 index of region start
        const float4* s1 = (const float4*)Wt_hh + base4;
        const float4* s2 = (const float4*)Wa_hh + base4;
        uint2* d1 = (uint2*)g_Whh_bf + base4;
        uint2* d2 = (uint2*)(g_Whh_bf + WELEM) + base4;
        const int n4 = nu * (H / 4);
        for (int e = tid; e < n4; e += NT) {
            float4 f = s1[e];
            __nv_bfloat162 p0 = __float22bfloat162_rn(make_float2(f.x, f.y));
            __nv_bfloat162 p1 = __float22bfloat162_rn(make_float2(f.z, f.w));
            uint2 o; o.x = *(unsigned*)&p0; o.y = *(unsigned*)&p1;
            d1[e] = o;
            f = s2[e];
            p0 = __float22bfloat162_rn(make_float2(f.x, f.y));
            p1 = __float22bfloat162_rn(make_float2(f.z, f.w));
            o.x = *(unsigned*)&p0; o.y = *(unsigned*)&p1;
            d2[e] = o;
        }
    }
    if (tid < UPB) { cT[tid] = 0.f; cA[tid] = 0.f; }
    __syncthreads();

    unsigned bar = 0;

    // ---- recurrence ----
    for (int t = 0; t < TT; t++) {
        stage_h_split(shA4, shB4, g_h_t + (size_t)(t & 1) * H, tid);
        __syncthreads();
        do_rows(g_Whh_bf, g_gx_t + (size_t)t * G, sgT, shA4, shB4, u0, nu, warp, lane);
        __syncthreads();
        if (t < TA) {
            stage_h_split(shA4, shB4, g_h_a + (size_t)(t & 1) * H, tid);
            __syncthreads();
            do_rows(g_Whh_bf + WELEM, g_gx_a + (size_t)t * G, sgA, shA4, shB4, u0, nu, warp, lane);
            __syncthreads();
        }
        if (tid < nu) {
            pointwise(sgT, cT, g_h_t + (size_t)((t + 1) & 1) * H + u0 + tid, tid);
            if (t < TA)
                pointwise(sgA, cA, g_h_a + (size_t)((t + 1) & 1) * H + u0 + tid, tid);
        }
        bar++;
        grid_barrier(bar);
    }
    // final title h in g_h_t[0..H) (128 even), final authors h in g_h_a[0..H) (16 even)

    // ---- MLP layer 1: h1 = relu([hT;hA] @ W1^T + b1) ----
    {
        const float4* t4 = (const float4*)g_h_t;
        const float4* a4 = (const float4*)g_h_a;
        float4* d4 = (float4*)sh;
        for (int i = tid; i < H / 4; i += NT) {
            d4[i]         = __ldcg(t4 + i);
            d4[H / 4 + i] = __ldcg(a4 + i);
        }
        __syncthreads();
        for (int r = warp; r < nu; r += 16) {
            int row = u0 + r;
            float s = warp_dot(W1 + (size_t)row * 2 * H, sh, 2 * H, lane);
            if (lane == 0) g_h1[row] = fmaxf(s + __ldg(b1 + row), 0.f);
        }
        bar++;
        grid_barrier(bar);
    }
    // ---- MLP layer 2 ----
    {
        const float4* s4 = (const float4*)g_h1;
        float4* d4 = (float4*)sh;
        for (int i = tid; i < H / 4; i += NT) d4[i] = __ldcg(s4 + i);
        __syncthreads();
        for (int r = warp; r < nu; r += 16) {
            int row = u0 + r;
            float s = warp_dot(W2 + (size_t)row * H, sh, H, lane);
            if (lane == 0) g_h2[row] = fmaxf(s + __ldg(b2 + row), 0.f);
        }
        bar++;
        grid_barrier(bar);
    }
    // ---- MLP layer 3 (block 0 only) ----
    if (b == 0) {
        const float4* s4 = (const float4*)g_h2;
        float4* d4 = (float4*)sh;
        for (int i = tid; i < H / 4; i += NT) d4[i] = __ldcg(s4 + i);
        __syncthreads();
        if (warp < 2) {
            float s = warp_dot(W3 + (size_t)warp * H, sh, H, lane);
            if (lane == 0) out[warp] = s + __ldg(b3 + warp);
        }
    }
}

// ---------------- launcher ----------------
extern "C" void kernel_launch(void* const* d_in, const int* in_sizes, int n_in,
                              void* d_out, int out_size) {
    const int*   x_title   = (const int*)  d_in[0];
    const int*   x_authors = (const int*)  d_in[1];
    const float* emb_t     = (const float*)d_in[2];
    const float* emb_a     = (const float*)d_in[3];
    const float* W_ih_t    = (const float*)d_in[4];
    const float* W_hh_t    = (const float*)d_in[5];
    const float* b_ih_t    = (const float*)d_in[6];
    const float* b_hh_t    = (const float*)d_in[7];
    const float* W_ih_a    = (const float*)d_in[8];
    const float* W_hh_a    = (const float*)d_in[9];
    const float* b_ih_a    = (const float*)d_in[10];
    const float* b_hh_a    = (const float*)d_in[11];
    const float* W1        = (const float*)d_in[12];
    const float* b1        = (const float*)d_in[13];
    const float* W2        = (const float*)d_in[14];
    const float* b2        = (const float*)d_in[15];
    const float* W3        = (const float*)d_in[16];
    const float* b3        = (const float*)d_in[17];
    float* out = (float*)d_out;

    init_kernel<<<(4 * H + 255) / 256, 256>>>();
    gemm_x_kernel<8><<<G / 64, 256>>>(x_title,   emb_t, W_ih_t, b_ih_t, b_hh_t);
    gemm_x_kernel<1><<<G / 64, 256>>>(x_authors, emb_a, W_ih_a, b_ih_a, b_hh_a);
    lstm_persist_kernel<<<NB, NT>>>(W_hh_t, W_hh_a, W1, b1, W2, b2, W3, b3, out);
}

// round 12
// speedup vs baseline: 1.2358x; 1.0414x over previous
#include <cuda_runtime.h>
#include <cuda_bf16.h>
#include <math.h>

// Problem dims (fixed by the reference)
#define E     1024
#define H     2048
#define G     8192     // 4*H gate rows
#define TT    128      // title timesteps
#define TA    16       // author timesteps
#define NB    148      // persistent grid: one block per SM
#define NT    512      // threads per block (16 warps)
#define UPB   14       // hidden units per block (148*14 = 2072 >= 2048)
#define WELEM ((size_t)G * H)

// ---------------- device scratch (no allocation allowed) ----------------
__device__ __align__(16) float g_gx_t[TT * G];
__device__ __align__(16) float g_gx_a[TA * G];
__device__ __align__(16) __nv_bfloat16 g_Whh_bf[2 * WELEM];  // [0]=title [1]=authors
__device__ __align__(16) float g_h_t[2 * H];
__device__ __align__(16) float g_h_a[2 * H];
__device__ __align__(16) float g_h1[H];
__device__ __align__(16) float g_h2[H];
__device__ unsigned g_arrive;
__device__ unsigned g_gen;

// ---------------- packed f32x2 + bf16 helpers ----------------
typedef unsigned long long ull;
__device__ __forceinline__ ull packf2(float x, float y) {
    ull d; asm("mov.b64 %0, {%1, %2};" : "=l"(d) : "f"(x), "f"(y)); return d;
}
__device__ __forceinline__ void unpackf2(ull d, float& x, float& y) {
    asm("mov.b64 {%0, %1}, %2;" : "=f"(x), "=f"(y) : "l"(d));
}
__device__ __forceinline__ void ffma2(ull& d, ull a, ull b) {
    asm("fma.rn.f32x2 %0, %1, %2, %0;" : "+l"(d) : "l"(a), "l"(b));
}
__device__ __forceinline__ ull addf2(ull a, ull b) {
    ull d; asm("add.rn.f32x2 %0, %1, %2;" : "=l"(d) : "l"(a), "l"(b)); return d;
}
__device__ __forceinline__ ull b2f2(unsigned w) {     // bf16x2 -> f32x2 via 2 PRMT
    unsigned lo, hi, z = 0u;
    asm("prmt.b32 %0, %1, %2, 0x1044;" : "=r"(lo) : "r"(w), "r"(z));
    asm("prmt.b32 %0, %1, %2, 0x3244;" : "=r"(hi) : "r"(w), "r"(z));
    ull d; asm("mov.b64 %0, {%1, %2};" : "=l"(d) : "r"(lo), "r"(hi));
    return d;
}

// ---------------- fence-free release/acquire grid barrier ----------------
__device__ __forceinline__ void bar_arrive(unsigned target) {
    unsigned old;
    asm volatile("atom.acq_rel.gpu.add.u32 %0, [%1], %2;"
                 : "=r"(old) : "l"(&g_arrive), "r"(1u) : "memory");
    if (old == NB - 1) {
        asm volatile("st.relaxed.gpu.u32 [%0], %1;" :: "l"(&g_arrive), "r"(0u) : "memory");
        asm volatile("st.release.gpu.u32 [%0], %1;" :: "l"(&g_gen), "r"(target) : "memory");
    }
}
__device__ __forceinline__ void bar_wait(unsigned target) {
    unsigned g;
    do {
        asm volatile("ld.acquire.gpu.u32 %0, [%1];" : "=r"(g) : "l"(&g_gen) : "memory");
    } while (g < target);
}
__device__ __forceinline__ void grid_sync(unsigned target) {
    __syncthreads();
    if (threadIdx.x == 0) { bar_arrive(target); bar_wait(target); }
    __syncthreads();
}

// ---------------- init: zero h buffers + barrier counters ----------------
__global__ void init_kernel() {
    int i = blockIdx.x * blockDim.x + threadIdx.x;
    if (i < 2 * H)          g_h_t[i] = 0.f;
    else if (i < 4 * H)     g_h_a[i - 2 * H] = 0.f;
    if (i == 0) { g_arrive = 0u; g_gen = 0u; }
}

// ---------------- x-side GEMM (gather fused) ----------------
template<int TR>
__global__ __launch_bounds__(256) void gemm_x_kernel(const int* __restrict__ idx,
                                                     const float* __restrict__ emb,
                                                     const float* __restrict__ W,
                                                     const float* __restrict__ bih,
                                                     const float* __restrict__ bhh) {
    constexpr int TTILE = 16 * TR;
    float* __restrict__ C = (TR == 8) ? g_gx_t : g_gx_a;

    __shared__ float Xs[32][TTILE + 4];
    __shared__ float Ws[32][68];
    __shared__ int idx_s[TTILE];

    const int tid = threadIdx.x;
    const int j0 = blockIdx.x * 64;
    for (int i = tid; i < TTILE; i += 256) idx_s[i] = idx[i];
    __syncthreads();

    const int jj = (tid & 15) * 4;
    const int ti = (tid >> 4) * TR;

    float acc[4][TR];
#pragma unroll
    for (int a = 0; a < 4; a++)
#pragma unroll
        for (int t = 0; t < TR; t++) acc[a][t] = 0.f;

    for (int k0 = 0; k0 < E; k0 += 32) {
        for (int e = tid; e < 32 * TTILE; e += 256) {
            int k = e & 31, t = e >> 5;
            Xs[k][t] = emb[(size_t)idx_s[t] * E + k0 + k];
        }
        for (int e = tid; e < 2048; e += 256) {
            int k = e & 31, j = e >> 5;
            Ws[k][j] = W[(size_t)(j0 + j) * E + k0 + k];
        }
        __syncthreads();
#pragma unroll
        for (int k = 0; k < 32; k++) {
            float4 wv = *(const float4*)&Ws[k][jj];
            if constexpr (TR == 8) {
                float4 x0 = *(const float4*)&Xs[k][ti];
                float4 x1 = *(const float4*)&Xs[k][ti + 4];
                float xv[8] = {x0.x, x0.y, x0.z, x0.w, x1.x, x1.y, x1.z, x1.w};
                float wa[4] = {wv.x, wv.y, wv.z, wv.w};
#pragma unroll
                for (int a = 0; a < 4; a++)
#pragma unroll
                    for (int t = 0; t < 8; t++) acc[a][t] = fmaf(wa[a], xv[t], acc[a][t]);
            } else {
                float xv = Xs[k][ti];
                acc[0][0] = fmaf(wv.x, xv, acc[0][0]);
                acc[1][0] = fmaf(wv.y, xv, acc[1][0]);
                acc[2][0] = fmaf(wv.z, xv, acc[2][0]);
                acc[3][0] = fmaf(wv.w, xv, acc[3][0]);
            }
        }
        __syncthreads();
    }

#pragma unroll
    for (int a = 0; a < 4; a++) {
        int j = j0 + jj + a;
        float bias = bih[j] + bhh[j];
#pragma unroll
        for (int t = 0; t < TR; t++)
            C[(size_t)(ti + t) * G + j] = acc[a][t] + bias;
    }
}

// ---------------- recurrence helpers ----------------
// split-stage h: A[c]=h4[2c], B[c]=h4[2c+1], c in [0,256)
__device__ __forceinline__ void stage_h_split(float4* A, float4* B, const float* src, int tid) {
    const float4* s4 = (const float4*)src;
    for (int i = tid; i < H / 8; i += NT) {
        A[i] = __ldcg(s4 + 2 * i);
        B[i] = __ldcg(s4 + 2 * i + 1);
    }
}

__device__ __forceinline__ void load_pair(uint4 va[8], uint4 vb[8],
                                          const __nv_bfloat16* __restrict__ Wb,
                                          int u0, int q, int lane) {
    const int r0 = 2 * q, r1 = r0 + 1;
    const uint4* wa = (const uint4*)(Wb + ((size_t)(r0 & 3) * H + u0 + (r0 >> 2)) * H);
    const uint4* wb = (const uint4*)(Wb + ((size_t)(r1 & 3) * H + u0 + (r1 >> 2)) * H);
#pragma unroll
    for (int k = 0; k < 8; k++) {
        va[k] = wa[(k << 5) + lane];
        vb[k] = wb[(k << 5) + lane];
    }
}

__device__ __forceinline__ void compute_pair(const uint4 va[8], const uint4 vb[8],
                                             const float4* __restrict__ A,
                                             const float4* __restrict__ B,
                                             const float* __restrict__ gx,
                                             float* __restrict__ sg,
                                             int u0, int q, int lane) {
    const int r0 = 2 * q, r1 = r0 + 1;
    ull a0 = 0, a1 = 0, b0 = 0, b1 = 0;
#pragma unroll
    for (int k = 0; k < 8; k++) {
        int c = (k << 5) + lane;
        float4 hA = A[c], hB = B[c];
        ull h0 = packf2(hA.x, hA.y), h1 = packf2(hA.z, hA.w);
        ull h2 = packf2(hB.x, hB.y), h3 = packf2(hB.z, hB.w);
        ffma2(a0, b2f2(va[k].x), h0); ffma2(a1, b2f2(va[k].y), h1);
        ffma2(a0, b2f2(va[k].z), h2); ffma2(a1, b2f2(va[k].w), h3);
        ffma2(b0, b2f2(vb[k].x), h0); ffma2(b1, b2f2(vb[k].y), h1);
        ffma2(b0, b2f2(vb[k].z), h2); ffma2(b1, b2f2(vb[k].w), h3);
    }
    float xa, ya, xb, yb;
    unpackf2(addf2(a0, a1), xa, ya);
    unpackf2(addf2(b0, b1), xb, yb);
    float sa = xa + ya, sb = xb + yb;
#pragma unroll
    for (int off = 16; off; off >>= 1) {
        sa += __shfl_xor_sync(0xFFFFFFFFu, sa, off);
        sb += __shfl_xor_sync(0xFFFFFFFFu, sb, off);
    }
    if (lane == 0) {
        sg[r0] = sa + __ldg(gx + (size_t)(r0 & 3) * H + u0 + (r0 >> 2));
        sg[r1] = sb + __ldg(gx + (size_t)(r1 & 3) * H + u0 + (r1 >> 2));
    }
}

__device__ __forceinline__ void pointwise(const float* sg, float* c_s, float* h_dst, int u) {
    float gi = sg[4 * u + 0];
    float gf = sg[4 * u + 1];
    float gg = sg[4 * u + 2];
    float go = sg[4 * u + 3];
    float iv = 1.f / (1.f + expf(-gi));
    float fv = 1.f / (1.f + expf(-gf));
    float gv = tanhf(gg);
    float ov = 1.f / (1.f + expf(-go));
    float cn = fv * c_s[u] + iv * gv;
    c_s[u] = cn;
    __stcg(h_dst, ov * tanhf(cn));
}

__device__ __forceinline__ float warp_dot(const float* __restrict__ Wrow,
                                          const float* __restrict__ shv, int K, int lane) {
    const float4* w4 = (const float4*)Wrow;
    const float4* s4 = (const float4*)shv;
    float acc = 0.f;
    for (int i = lane; i < K / 4; i += 32) {
        float4 w = w4[i], x = s4[i];
        acc = fmaf(w.x, x.x, fmaf(w.y, x.y, fmaf(w.z, x.z, fmaf(w.w, x.w, acc))));
    }
#pragma unroll
    for (int off = 16; off; off >>= 1) acc += __shfl_xor_sync(0xFFFFFFFFu, acc, off);
    return acc;
}

// ---------------- persistent kernel ----------------
__global__ __launch_bounds__(NT, 1) void lstm_persist_kernel(
        const float* __restrict__ Wt_hh, const float* __restrict__ Wa_hh,
        const float* __restrict__ W1, const float* __restrict__ b1,
        const float* __restrict__ W2, const float* __restrict__ b2,
        const float* __restrict__ W3, const float* __restrict__ b3,
        float* __restrict__ out) {
    __shared__ __align__(16) float sh[4 * H];       // 32 KB: hT split (16KB) + hA split (16KB); MLP reuses
    __shared__ float sgT[4 * UPB], sgA[4 * UPB];
    __shared__ float cT[UPB], cA[UPB];

    float4* shTA = (float4*)sh;                     // 256 entries
    float4* shTB = (float4*)(sh + H);
    float4* shAA = (float4*)(sh + 2 * H);
    float4* shAB = (float4*)(sh + 3 * H);

    const int tid = threadIdx.x, warp = tid >> 5, lane = tid & 31;
    const int b = blockIdx.x;
    const int u0 = b * UPB;
    int nu = 2048 - u0;
    if (nu < 0) nu = 0;
    if (nu > UPB) nu = UPB;
    const int npair = 2 * nu;

    // ---- prologue: convert OWN rows of both W_hh to bf16 ----
#pragma unroll
    for (int g = 0; g < 4; g++) {
        size_t base4 = (((size_t)g * H + u0) * H) >> 2;
        const float4* s1 = (const float4*)Wt_hh + base4;
        const float4* s2 = (const float4*)Wa_hh + base4;
        uint2* d1 = (uint2*)g_Whh_bf + base4;
        uint2* d2 = (uint2*)(g_Whh_bf + WELEM) + base4;
        const int n4 = nu * (H / 4);
        for (int e = tid; e < n4; e += NT) {
            float4 f = s1[e];
            __nv_bfloat162 p0 = __float22bfloat162_rn(make_float2(f.x, f.y));
            __nv_bfloat162 p1 = __float22bfloat162_rn(make_float2(f.z, f.w));
            uint2 o; o.x = *(unsigned*)&p0; o.y = *(unsigned*)&p1;
            d1[e] = o;
            f = s2[e];
            p0 = __float22bfloat162_rn(make_float2(f.x, f.y));
            p1 = __float22bfloat162_rn(make_float2(f.z, f.w));
            o.x = *(unsigned*)&p0; o.y = *(unsigned*)&p1;
            d2[e] = o;
        }
    }
    if (tid < UPB) { cT[tid] = 0.f; cA[tid] = 0.f; }

    unsigned bar = 0;
    uint4 pfa[8], pfb[8];                 // prefetched weights for first task (title pair q=warp)
    const bool has_pf = (warp < npair);   // warp < 16 <= 28, so first task is always a title pair
    if (has_pf) load_pair(pfa, pfb, g_Whh_bf, u0, warp, lane);
    grid_sync(++bar);                     // conversion complete chip-wide before first step

    // ---- recurrence ----
    for (int t = 0; t < TT; t++) {
        stage_h_split(shTA, shTB, g_h_t + (size_t)(t & 1) * H, tid);
        if (t < TA) stage_h_split(shAA, shAB, g_h_a + (size_t)(t & 1) * H, tid);
        __syncthreads();

        const float* gxT = g_gx_t + (size_t)t * G;
        const float* gxA = g_gx_a + (size_t)t * G;

        // iter 0: prefetched title pair q=warp
        if (has_pf) compute_pair(pfa, pfb, shTA, shTB, gxT, sgT, u0, warp, lane);
        const int ntask = (t < TA) ? 56 : 28;
        for (int p = warp + 16; p < ntask; p += 16) {
            const int s = (p >= 28);
            const int q = s ? p - 28 : p;
            if (q >= npair) continue;
            uint4 va[8], vb[8];
            load_pair(va, vb, g_Whh_bf + (s ? WELEM : 0), u0, q, lane);
            compute_pair(va, vb, s ? shAA : shTA, s ? shAB : shTB,
                         s ? gxA : gxT, s ? sgA : sgT, u0, q, lane);
        }
        __syncthreads();

        ++bar;
        if (warp == 0) {
            if (lane < nu) {
                pointwise(sgT, cT, g_h_t + (size_t)((t + 1) & 1) * H + u0 + lane, lane);
                if (t < TA)
                    pointwise(sgA, cA, g_h_a + (size_t)((t + 1) & 1) * H + u0 + lane, lane);
            }
            __syncwarp(0xFFFFFFFFu);
            if (lane == 0) bar_arrive(bar);
        }
        // prefetch next step's first title pair while the barrier drains
        if (has_pf) load_pair(pfa, pfb, g_Whh_bf, u0, warp, lane);
        if (tid == 0) bar_wait(bar);
        __syncthreads();
    }
    // final hT in g_h_t[0..H), final hA in g_h_a[0..H)  (TT, TA even)

    // ---- MLP layer 1: h1 = relu([hT;hA] @ W1^T + b1) ----
    {
        const float4* t4 = (const float4*)g_h_t;
        const float4* a4 = (const float4*)g_h_a;
        float4* d4 = (float4*)sh;
        for (int i = tid; i < H / 4; i += NT) {
            d4[i]         = __ldcg(t4 + i);
            d4[H / 4 + i] = __ldcg(a4 + i);
        }
        __syncthreads();
        if (warp < nu) {
            int row = u0 + warp;
            float s = warp_dot(W1 + (size_t)row * 2 * H, sh, 2 * H, lane);
            if (lane == 0) __stcg(&g_h1[row], fmaxf(s + __ldg(b1 + row), 0.f));
        }
        grid_sync(++bar);
    }
    // ---- MLP layer 2 ----
    {
        const float4* s4 = (const float4*)g_h1;
        float4* d4 = (float4*)sh;
        for (int i = tid; i < H / 4; i += NT) d4[i] = __ldcg(s4 + i);
        __syncthreads();
        if (warp < nu) {
            int row = u0 + warp;
            float s = warp_dot(W2 + (size_t)row * H, sh, H, lane);
            if (lane == 0) __stcg(&g_h2[row], fmaxf(s + __ldg(b2 + row), 0.f));
        }
        grid_sync(++bar);
    }
    // ---- MLP layer 3 (block 0 only) ----
    if (b == 0) {
        const float4* s4 = (const float4*)g_h2;
        float4* d4 = (float4*)sh;
        for (int i = tid; i < H / 4; i += NT) d4[i] = __ldcg(s4 + i);
        __syncthreads();
        if (warp < 2) {
            float s = warp_dot(W3 + (size_t)warp * H, sh, H, lane);
            if (lane == 0) out[warp] = s + __ldg(b3 + warp);
        }
    }
}

// ---------------- launcher ----------------
extern "C" void kernel_launch(void* const* d_in, const int* in_sizes, int n_in,
                              void* d_out, int out_size) {
    const int*   x_title   = (const int*)  d_in[0];
    const int*   x_authors = (const int*)  d_in[1];
    const float* emb_t     = (const float*)d_in[2];
    const float* emb_a     = (const float*)d_in[3];
    const float* W_ih_t    = (const float*)d_in[4];
    const float* W_hh_t    = (const float*)d_in[5];
    const float* b_ih_t    = (const float*)d_in[6];
    const float* b_hh_t    = (const float*)d_in[7];
    const float* W_ih_a    = (const float*)d_in[8];
    const float* W_hh_a    = (const float*)d_in[9];
    const float* b_ih_a    = (const float*)d_in[10];
    const float* b_hh_a    = (const float*)d_in[11];
    const float* W1        = (const float*)d_in[12];
    const float* b1        = (const float*)d_in[13];
    const float* W2        = (const float*)d_in[14];
    const float* b2        = (const float*)d_in[15];
    const float* W3        = (const float*)d_in[16];
    const float* b3        = (const float*)d_in[17];
    float* out = (float*)d_out;

    init_kernel<<<(4 * H + 255) / 256, 256>>>();
    gemm_x_kernel<8><<<G / 64, 256>>>(x_title,   emb_t, W_ih_t, b_ih_t, b_hh_t);
    gemm_x_kernel<1><<<G / 64, 256>>>(x_authors, emb_a, W_ih_a, b_ih_a, b_hh_a);
    lstm_persist_kernel<<<NB, NT>>>(W_hh_t, W_hh_a, W1, b1, W2, b2, W3, b3, out);
}

// round 13
// speedup vs baseline: 1.2378x; 1.0017x over previous
#include <cuda_runtime.h>
#include <cuda_bf16.h>
#include <math.h>

// Problem dims (fixed by the reference)
#define E     1024
#define H     2048
#define G     8192     // 4*H gate rows
#define TT    128      // title timesteps
#define TA    16       // author timesteps
#define NB    148      // persistent grid: one block per SM
#define NT    512      // threads per block (16 warps)
#define UPB   14       // hidden units per block (148*14 = 2072 >= 2048)
#define SMU   13       // units whose title weights live in smem (52 rows = 208 KB bf16)
#define WELEM ((size_t)G * H)
#define WS_BYTES (SMU * 4 * H * 2)          // 212992 B of smem weights
#define DYN_SMEM (WS_BYTES + 2 * H * 4)     // + 8 KB h staging = 221184 B

// ---------------- device scratch (no allocation allowed) ----------------
__device__ __align__(16) float g_gx_t[TT * G];
__device__ __align__(16) float g_gx_a[TA * G];
__device__ __align__(16) __nv_bfloat16 g_Wa_bf[WELEM];   // authors bf16 (32 MB)
__device__ __align__(16) float g_h_t[2 * H];
__device__ __align__(16) float g_h_a[2 * H];
__device__ __align__(16) float g_h1[H];
__device__ __align__(16) float g_h2[H];
__device__ unsigned g_arrive;
__device__ unsigned g_gen;

// ---------------- packed f32x2 + bf16 helpers ----------------
typedef unsigned long long ull;
__device__ __forceinline__ ull packf2(float x, float y) {
    ull d; asm("mov.b64 %0, {%1, %2};" : "=l"(d) : "f"(x), "f"(y)); return d;
}
__device__ __forceinline__ void unpackf2(ull d, float& x, float& y) {
    asm("mov.b64 {%0, %1}, %2;" : "=f"(x), "=f"(y) : "l"(d));
}
__device__ __forceinline__ void ffma2(ull& d, ull a, ull b) {
    asm("fma.rn.f32x2 %0, %1, %2, %0;" : "+l"(d) : "l"(a), "l"(b));
}
__device__ __forceinline__ ull addf2(ull a, ull b) {
    ull d; asm("add.rn.f32x2 %0, %1, %2;" : "=l"(d) : "l"(a), "l"(b)); return d;
}
__device__ __forceinline__ ull b2f2(unsigned w) {     // bf16x2 -> f32x2 via 2 PRMT
    unsigned lo, hi, z = 0u;
    asm("prmt.b32 %0, %1, %2, 0x1044;" : "=r"(lo) : "r"(w), "r"(z));
    asm("prmt.b32 %0, %1, %2, 0x3244;" : "=r"(hi) : "r"(w), "r"(z));
    ull d; asm("mov.b64 %0, {%1, %2};" : "=l"(d) : "r"(lo), "r"(hi));
    return d;
}

// ---------------- fence-free release/acquire grid barrier ----------------
__device__ __forceinline__ void bar_arrive(unsigned target) {
    unsigned old;
    asm volatile("atom.acq_rel.gpu.add.u32 %0, [%1], %2;"
                 : "=r"(old) : "l"(&g_arrive), "r"(1u) : "memory");
    if (old == NB - 1) {
        asm volatile("st.relaxed.gpu.u32 [%0], %1;" :: "l"(&g_arrive), "r"(0u) : "memory");
        asm volatile("st.release.gpu.u32 [%0], %1;" :: "l"(&g_gen), "r"(target) : "memory");
    }
}
__device__ __forceinline__ void bar_wait(unsigned target) {
    unsigned g;
    do {
        asm volatile("ld.acquire.gpu.u32 %0, [%1];" : "=r"(g) : "l"(&g_gen) : "memory");
    } while (g < target);
}
__device__ __forceinline__ void grid_sync(unsigned target) {
    __syncthreads();
    if (threadIdx.x == 0) { bar_arrive(target); bar_wait(target); }
    __syncthreads();
}

// ---------------- init: zero h buffers + barrier counters ----------------
__global__ void init_kernel() {
    int i = blockIdx.x * blockDim.x + threadIdx.x;
    if (i < 2 * H)          g_h_t[i] = 0.f;
    else if (i < 4 * H)     g_h_a[i - 2 * H] = 0.f;
    if (i == 0) { g_arrive = 0u; g_gen = 0u; }
}

// ---------------- title x-GEMM: 128 blocks (single wave), f32x2 packed ----------------
// tile: 64 j x 128 t, 256 threads, thread tile 4j x 8t (4 f32x2 pairs)
__global__ __launch_bounds__(256) void gemm_title_kernel(const int* __restrict__ idx,
                                                         const float* __restrict__ emb,
                                                         const float* __restrict__ W,
                                                         const float* __restrict__ bih,
                                                         const float* __restrict__ bhh) {
    __shared__ float Xs[32][136];   // [k][t], stride 544B (16B aligned)
    __shared__ float Ws[32][68];    // [k][j]
    __shared__ int idxs[128];

    const int tid = threadIdx.x;
    const int j0 = blockIdx.x * 64;
    for (int i = tid; i < 128; i += 256) idxs[i] = idx[i];
    __syncthreads();

    const int jj = (tid & 15) * 4;
    const int ti = (tid >> 4) * 8;

    ull acc[4][4];
#pragma unroll
    for (int a = 0; a < 4; a++)
#pragma unroll
        for (int b = 0; b < 4; b++) acc[a][b] = 0ull;

    for (int k0 = 0; k0 < E; k0 += 32) {
        for (int e = tid; e < 32 * 128; e += 256) {
            int k = e & 31, t = e >> 5;
            Xs[k][t] = emb[(size_t)idxs[t] * E + k0 + k];
        }
        for (int e = tid; e < 2048; e += 256) {
            int k = e & 31, j = e >> 5;
            Ws[k][j] = W[(size_t)(j0 + j) * E + k0 + k];
        }
        __syncthreads();
#pragma unroll
        for (int k = 0; k < 32; k++) {
            float4 w = *(const float4*)&Ws[k][jj];
            float4 x0 = *(const float4*)&Xs[k][ti];
            float4 x1 = *(const float4*)&Xs[k][ti + 4];
            ull xp[4] = {packf2(x0.x, x0.y), packf2(x0.z, x0.w),
                         packf2(x1.x, x1.y), packf2(x1.z, x1.w)};
            ull wp[4] = {packf2(w.x, w.x), packf2(w.y, w.y),
                         packf2(w.z, w.z), packf2(w.w, w.w)};
#pragma unroll
            for (int a = 0; a < 4; a++)
#pragma unroll
                for (int b = 0; b < 4; b++) ffma2(acc[a][b], wp[a], xp[b]);
        }
        __syncthreads();
    }

#pragma unroll
    for (int a = 0; a < 4; a++) {
        int j = j0 + jj + a;
        float bias = bih[j] + bhh[j];
#pragma unroll
        for (int b = 0; b < 4; b++) {
            float lo, hi;
            unpackf2(acc[a][b], lo, hi);
            g_gx_t[(size_t)(ti + 2 * b) * G + j]     = lo + bias;
            g_gx_t[(size_t)(ti + 2 * b + 1) * G + j] = hi + bias;
        }
    }
}

// ---------------- author x-GEMM: 128 blocks, tile 64 j x 16 t ----------------
__global__ __launch_bounds__(256) void gemm_auth_kernel(const int* __restrict__ idx,
                                                        const float* __restrict__ emb,
                                                        const float* __restrict__ W,
                                                        const float* __restrict__ bih,
                                                        const float* __restrict__ bhh) {
    __shared__ float Xa[32][20];    // [k][t] pad 20 (8B-aligned reads)
    __shared__ float Wa[32][68];
    __shared__ int idxs[16];

    const int tid = threadIdx.x;
    const int j0 = blockIdx.x * 64;
    if (tid < 16) idxs[tid] = idx[tid];
    __syncthreads();

    const int jl = tid & 63;        // j within tile
    const int t0 = (tid >> 6) * 4;  // 4 t per thread (2 f32x2)

    ull acc0 = 0ull, acc1 = 0ull;

    for (int k0 = 0; k0 < E; k0 += 32) {
        for (int e = tid; e < 32 * 16; e += 256) {
            int k = e & 31, t = e >> 5;
            Xa[k][t] = emb[(size_t)idxs[t] * E + k0 + k];
        }
        for (int e = tid; e < 2048; e += 256) {
            int k = e & 31, j = e >> 5;
            Wa[k][j] = W[(size_t)(j0 + j) * E + k0 + k];
        }
        __syncthreads();
#pragma unroll
        for (int k = 0; k < 32; k++) {
            float w = Wa[k][jl];
            ull wp = packf2(w, w);
            ull x0 = *(const ull*)&Xa[k][t0];
            ull x1 = *(const ull*)&Xa[k][t0 + 2];
            ffma2(acc0, wp, x0);
            ffma2(acc1, wp, x1);
        }
        __syncthreads();
    }

    int j = j0 + jl;
    float bias = bih[j] + bhh[j];
    float lo, hi;
    unpackf2(acc0, lo, hi);
    g_gx_a[(size_t)(t0 + 0) * G + j] = lo + bias;
    g_gx_a[(size_t)(t0 + 1) * G + j] = hi + bias;
    unpackf2(acc1, lo, hi);
    g_gx_a[(size_t)(t0 + 2) * G + j] = lo + bias;
    g_gx_a[(size_t)(t0 + 3) * G + j] = hi + bias;
}

// ---------------- recurrence helpers ----------------
// split-stage h: A[c]=h4[2c], B[c]=h4[2c+1], c in [0,256)
__device__ __forceinline__ void stage_h_split(float4* A, float4* B, const float* src, int tid) {
    const float4* s4 = (const float4*)src;
    for (int i = tid; i < H / 8; i += NT) {
        A[i] = __ldcg(s4 + 2 * i);
        B[i] = __ldcg(s4 + 2 * i + 1);
    }
}

// pair q (<2*SMU): rows (2q,2q+1) = unit q>>1, gates (q&1)*2, +1. Weights from smem.
__device__ __forceinline__ void pair_smem(const __nv_bfloat16* __restrict__ ws,
                                          const float* __restrict__ gx,
                                          float* __restrict__ sg,
                                          const float4* __restrict__ A,
                                          const float4* __restrict__ B,
                                          int u0, int q, int lane) {
    const int ul = q >> 1, g0 = (q & 1) * 2;
    const uint4* w0 = (const uint4*)(ws + ((size_t)(ul * 4 + g0) << 11));
    const uint4* w1 = (const uint4*)(ws + ((size_t)(ul * 4 + g0 + 1) << 11));
    ull a0 = 0, a1 = 0, b0 = 0, b1 = 0;
#pragma unroll
    for (int k = 0; k < 8; k++) {
        int c = (k << 5) + lane;
        uint4 va = w0[c], vb = w1[c];
        float4 hA = A[c], hB = B[c];
        ull h0 = packf2(hA.x, hA.y), h1 = packf2(hA.z, hA.w);
        ull h2 = packf2(hB.x, hB.y), h3 = packf2(hB.z, hB.w);
        ffma2(a0, b2f2(va.x), h0); ffma2(a1, b2f2(va.y), h1);
        ffma2(a0, b2f2(va.z), h2); ffma2(a1, b2f2(va.w), h3);
        ffma2(b0, b2f2(vb.x), h0); ffma2(b1, b2f2(vb.y), h1);
        ffma2(b0, b2f2(vb.z), h2); ffma2(b1, b2f2(vb.w), h3);
    }
    float xa, ya, xb, yb;
    unpackf2(addf2(a0, a1), xa, ya);
    unpackf2(addf2(b0, b1), xb, yb);
    float sa = xa + ya, sb = xb + yb;
#pragma unroll
    for (int off = 16; off; off >>= 1) {
        sa += __shfl_xor_sync(0xFFFFFFFFu, sa, off);
        sb += __shfl_xor_sync(0xFFFFFFFFu, sb, off);
    }
    if (lane == 0) {
        sg[4 * ul + g0]     = sa + __ldg(gx + (size_t)g0 * H + u0 + ul);
        sg[4 * ul + g0 + 1] = sb + __ldg(gx + (size_t)(g0 + 1) * H + u0 + ul);
    }
}

// single fp32 row (unit ul=SMU..13, gate g) streamed from global fp32
__device__ __forceinline__ void row_f32(const float* __restrict__ Whh,
                                        const float* __restrict__ gx,
                                        float* __restrict__ sg,
                                        const float4* __restrict__ A,
                                        const float4* __restrict__ B,
                                        int u0, int ul, int g, int lane) {
    const float4* w4 = (const float4*)(Whh + ((size_t)g * H + u0 + ul) * H);
    float acc = 0.f;
#pragma unroll
    for (int half = 0; half < 2; half++) {
        float4 wb[8];
#pragma unroll
        for (int k = 0; k < 8; k++) wb[k] = __ldg(w4 + (((half * 8 + k) << 5) + lane));
#pragma unroll
        for (int k = 0; k < 8; k++) {
            int i = ((half * 8 + k) << 5) + lane;   // float4 idx 0..511
            float4 hv = (i & 1) ? B[i >> 1] : A[i >> 1];
            acc = fmaf(wb[k].x, hv.x, fmaf(wb[k].y, hv.y,
                  fmaf(wb[k].z, hv.z, fmaf(wb[k].w, hv.w, acc))));
        }
    }
#pragma unroll
    for (int off = 16; off; off >>= 1) acc += __shfl_xor_sync(0xFFFFFFFFu, acc, off);
    if (lane == 0) sg[4 * ul + g] = acc + __ldg(gx + (size_t)g * H + u0 + ul);
}

// author pair from global bf16, register-batched (L2 latency hiding)
__device__ __forceinline__ void pair_gbf16(const __nv_bfloat16* __restrict__ Wb,
                                           const float* __restrict__ gx,
                                           float* __restrict__ sg,
                                           const float4* __restrict__ A,
                                           const float4* __restrict__ B,
                                           int u0, int q, int lane) {
    const int ul = q >> 1, g0 = (q & 1) * 2;
    const uint4* w0 = (const uint4*)(Wb + ((size_t)g0 * H + u0 + ul) * H);
    const uint4* w1 = (const uint4*)(Wb + ((size_t)(g0 + 1) * H + u0 + ul) * H);
    uint4 va[8], vb[8];
#pragma unroll
    for (int k = 0; k < 8; k++) {
        va[k] = w0[(k << 5) + lane];
        vb[k] = w1[(k << 5) + lane];
    }
    ull a0 = 0, a1 = 0, b0 = 0, b1 = 0;
#pragma unroll
    for (int k = 0; k < 8; k++) {
        int c = (k << 5) + lane;
        float4 hA = A[c], hB = B[c];
        ull h0 = packf2(hA.x, hA.y), h1 = packf2(hA.z, hA.w);
        ull h2 = packf2(hB.x, hB.y), h3 = packf2(hB.z, hB.w);
        ffma2(a0, b2f2(va[k].x), h0); ffma2(a1, b2f2(va[k].y), h1);
        ffma2(a0, b2f2(va[k].z), h2); ffma2(a1, b2f2(va[k].w), h3);
        ffma2(b0, b2f2(vb[k].x), h0); ffma2(b1, b2f2(vb[k].y), h1);
        ffma2(b0, b2f2(vb[k].z), h2); ffma2(b1, b2f2(vb[k].w), h3);
    }
    float xa, ya, xb, yb;
    unpackf2(addf2(a0, a1), xa, ya);
    unpackf2(addf2(b0, b1), xb, yb);
    float sa = xa + ya, sb = xb + yb;
#pragma unroll
    for (int off = 16; off; off >>= 1) {
        sa += __shfl_xor_sync(0xFFFFFFFFu, sa, off);
        sb += __shfl_xor_sync(0xFFFFFFFFu, sb, off);
    }
    if (lane == 0) {
        sg[4 * ul + g0]     = sa + __ldg(gx + (size_t)g0 * H + u0 + ul);
        sg[4 * ul + g0 + 1] = sb + __ldg(gx + (size_t)(g0 + 1) * H + u0 + ul);
    }
}

__device__ __forceinline__ void pointwise(const float* sg, float* c_s, float* h_dst, int u) {
    float gi = sg[4 * u + 0];
    float gf = sg[4 * u + 1];
    float gg = sg[4 * u + 2];
    float go = sg[4 * u + 3];
    float iv = 1.f / (1.f + expf(-gi));
    float fv = 1.f / (1.f + expf(-gf));
    float gv = tanhf(gg);
    float ov = 1.f / (1.f + expf(-go));
    float cn = fv * c_s[u] + iv * gv;
    c_s[u] = cn;
    __stcg(h_dst, ov * tanhf(cn));
}

__device__ __forceinline__ float warp_dot(const float* __restrict__ Wrow,
                                          const float* __restrict__ shv, int K, int lane) {
    const float4* w4 = (const float4*)Wrow;
    const float4* s4 = (const float4*)shv;
    float acc = 0.f;
    for (int i = lane; i < K / 4; i += 32) {
        float4 w = w4[i], x = s4[i];
        acc = fmaf(w.x, x.x, fmaf(w.y, x.y, fmaf(w.z, x.z, fmaf(w.w, x.w, acc))));
    }
#pragma unroll
    for (int off = 16; off; off >>= 1) acc += __shfl_xor_sync(0xFFFFFFFFu, acc, off);
    return acc;
}

// ---------------- persistent kernel: convert + recurrence + MLP ----------------
__global__ __launch_bounds__(NT, 1) void lstm_persist_kernel(
        const float* __restrict__ Wt_hh, const float* __restrict__ Wa_hh,
        const float* __restrict__ W1, const float* __restrict__ b1,
        const float* __restrict__ W2, const float* __restrict__ b2,
        const float* __restrict__ W3, const float* __restrict__ b3,
        float* __restrict__ out) {
    extern __shared__ __align__(16) unsigned char dynsm[];
    __nv_bfloat16* ws = (__nv_bfloat16*)dynsm;            // 208 KB title weights
    float* hstage = (float*)(dynsm + WS_BYTES);           // 8 KB h staging
    float4* sA = (float4*)hstage;                         // 256 entries
    float4* sB = sA + 256;

    __shared__ float sgT[4 * UPB], sgA[4 * UPB];
    __shared__ float cT[UPB], cA[UPB];

    const int tid = threadIdx.x, warp = tid >> 5, lane = tid & 31;
    const int b = blockIdx.x;
    const int u0 = b * UPB;
    int nu = 2048 - u0;
    if (nu < 0) nu = 0;
    if (nu > UPB) nu = UPB;

    const int n_sm = (nu < SMU) ? nu : SMU;       // units in smem
    const int nsm_pairs = 2 * n_sm;
    const int nf32 = (nu > SMU) ? 4 * (nu - SMU) : 0;   // single fp32-row tasks
    const int ntitle = nsm_pairs + nf32;
    const int napair = 2 * nu;

    // ---- prologue A: convert own title rows fp32 -> smem bf16 (unit-major) ----
    {
        unsigned* wsu = (unsigned*)ws;
        const int total = n_sm * 4 * (H / 2);     // bf16x2 words
        for (int e = tid; e < total; e += NT) {
            int sr = e >> 10, w = e & 1023;       // H/2 = 1024 words per row
            int ul = sr >> 2, g = sr & 3;
            float2 v = *(const float2*)(Wt_hh + ((size_t)g * H + u0 + ul) * H + 2 * w);
            __nv_bfloat162 p = __float22bfloat162_rn(v);
            wsu[(sr << 10) + w] = *(unsigned*)&p;
        }
    }
    // ---- prologue B: cooperative author matrix fp32 -> global bf16 ----
    {
        const float2* src = (const float2*)Wa_hh;
        unsigned* dst = (unsigned*)g_Wa_bf;
        for (size_t i = (size_t)b * NT + tid; i < WELEM / 2; i += (size_t)NB * NT) {
            float2 v = src[i];
            __nv_bfloat162 p = __float22bfloat162_rn(v);
            dst[i] = *(unsigned*)&p;
        }
    }
    if (tid < UPB) { cT[tid] = 0.f; cA[tid] = 0.f; }

    unsigned bar = 0;
    grid_sync(++bar);   // conversions complete chip-wide

    // ---- recurrence ----
    for (int t = 0; t < TT; t++) {
        // title phase
        stage_h_split(sA, sB, g_h_t + (size_t)(t & 1) * H, tid);
        __syncthreads();
        const float* gxT = g_gx_t + (size_t)t * G;
        for (int p = warp; p < ntitle; p += 16) {
            if (p < nsm_pairs) pair_smem(ws, gxT, sgT, sA, sB, u0, p, lane);
            else {
                int r = p - nsm_pairs;
                row_f32(Wt_hh, gxT, sgT, sA, sB, u0, SMU + (r >> 2), r & 3, lane);
            }
        }
        __syncthreads();
        // author phase (re-stage same buffer)
        if (t < TA) {
            stage_h_split(sA, sB, g_h_a + (size_t)(t & 1) * H, tid);
            __syncthreads();
            const float* gxA = g_gx_a + (size_t)t * G;
            for (int p = warp; p < napair; p += 16)
                pair_gbf16(g_Wa_bf, gxA, sgA, sA, sB, u0, p, lane);
            __syncthreads();
        }
        // pointwise + barrier
        ++bar;
        if (warp == 0) {
            if (lane < nu) {
                pointwise(sgT, cT, g_h_t + (size_t)((t + 1) & 1) * H + u0 + lane, lane);
                if (t < TA)
                    pointwise(sgA, cA, g_h_a + (size_t)((t + 1) & 1) * H + u0 + lane, lane);
            }
            __syncwarp(0xFFFFFFFFu);
            if (lane == 0) { bar_arrive(bar); bar_wait(bar); }
        }
        __syncthreads();
    }
    // final hT in g_h_t[0..H), final hA in g_h_a[0..H)  (TT, TA even)

    float* mstage = (float*)dynsm;   // reuse weight smem (16 KB) for MLP staging

    // ---- MLP layer 1: h1 = relu([hT;hA] @ W1^T + b1) ----
    {
        const float4* t4 = (const float4*)g_h_t;
        const float4* a4 = (const float4*)g_h_a;
        float4* d4 = (float4*)mstage;
        for (int i = tid; i < H / 4; i += NT) {
            d4[i]         = __ldcg(t4 + i);
            d4[H / 4 + i] = __ldcg(a4 + i);
        }
        __syncthreads();
        if (warp < nu) {
            int row = u0 + warp;
            float s = warp_dot(W1 + (size_t)row * 2 * H, mstage, 2 * H, lane);
            if (lane == 0) __stcg(&g_h1[row], fmaxf(s + __ldg(b1 + row), 0.f));
        }
        grid_sync(++bar);
    }
    // ---- MLP layer 2 ----
    {
        const float4* s4 = (const float4*)g_h1;
        float4* d4 = (float4*)mstage;
        for (int i = tid; i < H / 4; i += NT) d4[i] = __ldcg(s4 + i);
        __syncthreads();
        if (warp < nu) {
            int row = u0 + warp;
            float s = warp_dot(W2 + (size_t)row * H, mstage, H, lane);
            if (lane == 0) __stcg(&g_h2[row], fmaxf(s + __ldg(b2 + row), 0.f));
        }
        grid_sync(++bar);
    }
    // ---- MLP layer 3 (block 0 only) ----
    if (b == 0) {
        const float4* s4 = (const float4*)g_h2;
        float4* d4 = (float4*)mstage;
        for (int i = tid; i < H / 4; i += NT) d4[i] = __ldcg(s4 + i);
        __syncthreads();
        if (warp < 2) {
            float s = warp_dot(W3 + (size_t)warp * H, mstage, H, lane);
            if (lane == 0) out[warp] = s + __ldg(b3 + warp);
        }
    }
}

// ---------------- launcher ----------------
extern "C" void kernel_launch(void* const* d_in, const int* in_sizes, int n_in,
                              void* d_out, int out_size) {
    const int*   x_title   = (const int*)  d_in[0];
    const int*   x_authors = (const int*)  d_in[1];
    const float* emb_t     = (const float*)d_in[2];
    const float* emb_a     = (const float*)d_in[3];
    const float* W_ih_t    = (const float*)d_in[4];
    const float* W_hh_t    = (const float*)d_in[5];
    const float* b_ih_t    = (const float*)d_in[6];
    const float* b_hh_t    = (const float*)d_in[7];
    const float* W_ih_a    = (const float*)d_in[8];
    const float* W_hh_a    = (const float*)d_in[9];
    const float* b_ih_a    = (const float*)d_in[10];
    const float* b_hh_a    = (const float*)d_in[11];
    const float* W1        = (const float*)d_in[12];
    const float* b1        = (const float*)d_in[13];
    const float* W2        = (const float*)d_in[14];
    const float* b2        = (const float*)d_in[15];
    const float* W3        = (const float*)d_in[16];
    const float* b3        = (const float*)d_in[17];
    float* out = (float*)d_out;

    static int smem_set = 0;
    if (!smem_set) {
        cudaFuncSetAttribute(lstm_persist_kernel,
                             cudaFuncAttributeMaxDynamicSharedMemorySize, DYN_SMEM);
        smem_set = 1;
    }

    init_kernel<<<(4 * H + 255) / 256, 256>>>();
    gemm_title_kernel<<<128, 256>>>(x_title,   emb_t, W_ih_t, b_ih_t, b_hh_t);
    gemm_auth_kernel <<<128, 256>>>(x_authors, emb_a, W_ih_a, b_ih_a, b_hh_a);
    lstm_persist_kernel<<<NB, NT, DYN_SMEM>>>(W_hh_t, W_hh_a, W1, b1, W2, b2, W3, b3, out);
}